// round 16
// baseline (speedup 1.0000x reference)
#include <cuda_runtime.h>
#include <cuda_fp16.h>
#include <cstdint>

// ---------------- problem constants ----------------
#define B_    32
#define C_    256
#define O_    256
#define H_    49
#define P_    (H_ * H_)        // 2401
#define PAD   51
#define M_    (B_ * P_)        // 76832
#define KTOT  (7 * C_)         // 1792
#define KC    32               // K per pipeline chunk (2 x k16 mma steps)
#define NCHUNK (KTOT / KC)     // 56
#define STAGES 4
#define MT    128              // M rows per CTA
#define GRID_M ((M_ + MT - 1) / MT)   // 601

#define A_STRIDE 40                     // halfs per A row (80 B) - ldmatrix conflict-free
#define B_STRIDE 136                    // halfs per B k-row (272 B) - ldmatrix.trans conflict-free
#define A_STAGE_H (MT * A_STRIDE)       // 5120 halfs = 10240 B
#define B_STAGE_H (KC * B_STRIDE)       // 4352 halfs = 8704 B
#define DYN_SMEM (STAGES * (A_STAGE_H + B_STAGE_H) * 2)   // 75776 B (also > epilogue 67584)

// DIRS offsets in padded channels-last space: (dy*PAD+dx)*C_ (element counts)
__constant__ int c_tapoff[7] = { 0, 13056, 256, -12800, -13056, -256, 12800 };

// ---------------- scratch ----------------
__device__ __half g_xpad[B_ * PAD * PAD * C_];   // [B,51,51,C] channels-last, masked, fp16
__device__ __half g_wbT[KTOT * O_];              // [k][o], k = tap*256 + c, fp16

// ---------------- helpers ----------------
__device__ __forceinline__ void mma16(float* c, const uint32_t* a, const uint32_t* b) {
    asm volatile(
        "mma.sync.aligned.m16n8k16.row.col.f32.f16.f16.f32 "
        "{%0,%1,%2,%3}, {%4,%5,%6,%7}, {%8,%9}, {%0,%1,%2,%3};"
        : "+f"(c[0]), "+f"(c[1]), "+f"(c[2]), "+f"(c[3])
        : "r"(a[0]), "r"(a[1]), "r"(a[2]), "r"(a[3]), "r"(b[0]), "r"(b[1]));
}
#define LDSM_X4(r0, r1, r2, r3, addr)                                        \
    asm volatile("ldmatrix.sync.aligned.m8n8.x4.shared.b16 {%0,%1,%2,%3}, [%4];" \
        : "=r"(r0), "=r"(r1), "=r"(r2), "=r"(r3) : "r"(addr))
#define LDSM_X4T(r0, r1, r2, r3, addr)                                       \
    asm volatile("ldmatrix.sync.aligned.m8n8.x4.trans.shared.b16 {%0,%1,%2,%3}, [%4];" \
        : "=r"(r0), "=r"(r1), "=r"(r2), "=r"(r3) : "r"(addr))
#define CP_ASYNC16(dst, src) \
    asm volatile("cp.async.cg.shared.global [%0], [%1], 16;" :: "r"(dst), "l"(src))
#define CP_COMMIT() asm volatile("cp.async.commit_group;")
#define CP_WAIT(n)  asm volatile("cp.async.wait_group %0;" :: "n"(n))

// ---------------- prep kernels ----------------
__global__ void zero_halo_kernel() {      // zero the 200 boundary cells of xpad
    int t = blockIdx.x * blockDim.x + threadIdx.x;
    const int total = B_ * 200 * 32;      // 200 cells * 512 B = 32 uint4 each
    if (t >= total) return;
    int q = t & 31;
    int cell = (t >> 5) % 200;
    int b = t / (200 * 32);
    int h, w;
    if      (cell < 51)  { h = 0;  w = cell; }
    else if (cell < 102) { h = 50; w = cell - 51; }
    else if (cell < 151) { h = cell - 101; w = 0; }
    else                 { h = cell - 150; w = 50; }
    ((uint4*)(g_xpad + ((size_t)(b * PAD + h) * PAD + w) * C_))[q] =
        make_uint4(0u, 0u, 0u, 0u);
}

__global__ void prep_wb_kernel(const float* __restrict__ w) {
    int idx = blockIdx.x * blockDim.x + threadIdx.x;   // idx = k*256 + o
    if (idx < KTOT * O_) {
        int o = idx & 255;
        int k = idx >> 8;
        int tap = k >> 8, c = k & 255;
        g_wbT[idx] = __float2half_rn(w[(o * C_ + c) * 7 + tap]);
    }
}

__global__ void prep_x_kernel(const float* __restrict__ x) {
    __shared__ float tile[32][33];
    const int b = blockIdx.z, c0 = blockIdx.y * 32, hw0 = blockIdx.x * 32;
    const int tx = threadIdx.x, ty = threadIdx.y;
#pragma unroll
    for (int i = 0; i < 4; i++) {
        int c = c0 + ty + i * 8, hw = hw0 + tx;
        tile[ty + i * 8][tx] = (hw < P_) ? x[((size_t)b * C_ + c) * P_ + hw] : 0.f;
    }
    __syncthreads();
#pragma unroll
    for (int i = 0; i < 4; i++) {
        int hw = hw0 + ty + i * 8;
        if (hw < P_) {
            int h = hw / H_, w = hw - h * H_;
            bool mk = (unsigned)(h + w - 24) <= 48u;
            float v = mk ? tile[tx][ty + i * 8] : 0.f;
            g_xpad[((size_t)(b * PAD + h + 1) * PAD + (w + 1)) * C_ + c0 + tx] =
                __float2half_rn(v);
        }
    }
}

// ---------------- main: fp16 mma.sync m16n8k16, 128x128 tile, 4-stage cp.async ----------
__global__ __launch_bounds__(256, 2)
void hexconv_mma_kernel(const float* __restrict__ bias, float* __restrict__ out) {
    extern __shared__ __align__(16) char smraw[];
    __half* sA = (__half*)smraw;                              // [STAGES][128][40]
    __half* sB = (__half*)(smraw + STAGES * A_STAGE_H * 2);   // [STAGES][32][136]
    __shared__ int rbase[MT];

    const int tid = threadIdx.x, wid = tid >> 5, lane = tid & 31;
    const int r0 = blockIdx.x * MT;
    const int nb = blockIdx.y;                 // N tile: o-offset nb*128

    if (tid < MT) {
        int r = r0 + tid;
        if (r >= M_) r = M_ - 1;
        int b = r / P_, hw = r - b * P_, h = hw / H_, w = hw - h * H_;
        rbase[tid] = ((b * PAD + h + 1) * PAD + (w + 1)) * C_;
    }
    __syncthreads();

    // A loader: row = tid>>1 (0..127), two 16B chunks at q = (tid&1)*2, +1
    const int arow = tid >> 1;
    const int aq   = (tid & 1) * 2;            // chunk index (8 halfs each)
    const int raA  = rbase[arow];
    // B loader: row = tid>>3 (0..31), two 16B chunks at q = (tid&7)*2, +1
    const int brow = tid >> 3;
    const int bq   = (tid & 7) * 2;

    const uint32_t sA_u = (uint32_t)__cvta_generic_to_shared(sA);
    const uint32_t sB_u = (uint32_t)__cvta_generic_to_shared(sB);

    // warp tile: 2 (M) x 4 (N) warps, each 64x32
    const int wm = (wid & 1) * 64;
    const int wn = (wid >> 1) * 32;
    const int lq4 = lane & 3;
    const int lr4 = lane >> 2;

    // ldmatrix lane address components (halfs)
    const int a_lane_row = wm + (lane & 15);          // + mi*16
    const int a_lane_col = (lane >> 4) * 8;           // + kk*16
    const int b_lane_k   = (lane & 7) + ((lane >> 3) & 1) * 8;   // + kk*16
    const int b_lane_n   = wn + (lane >> 4) * 8;      // + pass*16

    float acc[4][4][4];
#pragma unroll
    for (int mi = 0; mi < 4; mi++)
#pragma unroll
        for (int ni = 0; ni < 4; ni++)
#pragma unroll
            for (int j = 0; j < 4; j++) acc[mi][ni][j] = 0.f;

    auto load_stage = [&](int s, int ch) {
        const int k0 = ch * KC;
        const int offA = c_tapoff[k0 >> 8] + (k0 & 255) + aq * 8;
        uint32_t dA = sA_u + (uint32_t)(s * A_STAGE_H + arow * A_STRIDE + aq * 8) * 2u;
        const __half* srcA = g_xpad + raA + offA;
        CP_ASYNC16(dA, srcA);
        CP_ASYNC16(dA + 16, srcA + 8);
        const __half* srcB = g_wbT + (size_t)(k0 + brow) * O_ + nb * 128 + bq * 8;
        uint32_t dB = sB_u + (uint32_t)(s * B_STAGE_H + brow * B_STRIDE + bq * 8) * 2u;
        CP_ASYNC16(dB, srcB);
        CP_ASYNC16(dB + 16, srcB + 8);
    };

#pragma unroll
    for (int s = 0; s < STAGES - 1; s++) { load_stage(s, s); CP_COMMIT(); }

    for (int ch = 0; ch < NCHUNK; ch++) {
        CP_WAIT(STAGES - 2);
        __syncthreads();
        const int pre = ch + STAGES - 1;
        if (pre < NCHUNK) load_stage(pre % STAGES, pre);
        CP_COMMIT();

        const uint32_t Ab = sA_u + (uint32_t)((ch % STAGES) * A_STAGE_H) * 2u;
        const uint32_t Bb = sB_u + (uint32_t)((ch % STAGES) * B_STAGE_H) * 2u;

#pragma unroll
        for (int kk = 0; kk < 2; kk++) {       // two k16 steps per 32-chunk
            uint32_t af[4][4];
#pragma unroll
            for (int mi = 0; mi < 4; mi++) {
                uint32_t addr = Ab + (uint32_t)((a_lane_row + mi * 16) * A_STRIDE
                                                + kk * 16 + a_lane_col) * 2u;
                LDSM_X4(af[mi][0], af[mi][1], af[mi][2], af[mi][3], addr);
            }
            uint32_t bf[4][2];
#pragma unroll
            for (int pass = 0; pass < 2; pass++) {
                uint32_t addr = Bb + (uint32_t)((kk * 16 + b_lane_k) * B_STRIDE
                                                + b_lane_n + pass * 16) * 2u;
                LDSM_X4T(bf[2 * pass][0], bf[2 * pass][1],
                         bf[2 * pass + 1][0], bf[2 * pass + 1][1], addr);
            }
#pragma unroll
            for (int mi = 0; mi < 4; mi++)
#pragma unroll
                for (int ni = 0; ni < 4; ni++)
                    mma16(acc[mi][ni], af[mi], bf[ni]);
        }
    }

    // ---- epilogue: acc -> smem [o][m] (stride 132), then coalesced store ----
    __syncthreads();
    float* ep = (float*)smraw;            // 128*132 floats = 67584 B < 75776 B
#pragma unroll
    for (int mi = 0; mi < 4; mi++) {
        int rrow = wm + mi * 16 + lr4;
#pragma unroll
        for (int ni = 0; ni < 4; ni++) {
            int o = wn + ni * 8 + 2 * lq4;
            ep[o * 132 + rrow]           = acc[mi][ni][0];
            ep[(o + 1) * 132 + rrow]     = acc[mi][ni][1];
            ep[o * 132 + rrow + 8]       = acc[mi][ni][2];
            ep[(o + 1) * 132 + rrow + 8] = acc[mi][ni][3];
        }
    }
    __syncthreads();

    for (int o = wid; o < 128; o += 8) {
        float bv = __ldg(bias + nb * 128 + o);
#pragma unroll
        for (int mb = 0; mb < 128; mb += 32) {
            int m = mb + lane;
            int r = r0 + m;
            if (r < M_) {
                int b = r / P_, hw = r - b * P_, h = hw / H_, w = hw - h * H_;
                bool mk = (unsigned)(h + w - 24) <= 48u;
                float v = mk ? (ep[o * 132 + m] + bv) : 0.f;
                out[((size_t)b * O_ + nb * 128 + o) * P_ + hw] = v;
            }
        }
    }
}

// ---------------- launcher ----------------
extern "C" void kernel_launch(void* const* d_in, const int* in_sizes, int n_in,
                              void* d_out, int out_size) {
    const float* x    = (const float*)d_in[0];   // [32,256,49,49]
    const float* wgt  = (const float*)d_in[1];   // [256,256,7]
    const float* bias = (const float*)d_in[2];   // [256]
    float* out = (float*)d_out;

    { // prep
        int nh = B_ * 200 * 32;
        zero_halo_kernel<<<(nh + 255) / 256, 256>>>();
        int nw = KTOT * O_;
        prep_wb_kernel<<<(nw + 255) / 256, 256>>>(wgt);
        dim3 g((P_ + 31) / 32, C_ / 32, B_);
        prep_x_kernel<<<g, dim3(32, 8)>>>(x);
    }

    cudaFuncSetAttribute(hexconv_mma_kernel,
                         cudaFuncAttributeMaxDynamicSharedMemorySize, DYN_SMEM);
    dim3 grid(GRID_M, 2);
    hexconv_mma_kernel<<<grid, 256, DYN_SMEM>>>(bias, out);
}

// round 17
// speedup vs baseline: 1.3581x; 1.3581x over previous
#include <cuda_runtime.h>
#include <cstdint>

// ---------------- problem constants ----------------
#define B_    32
#define C_    256
#define O_    256
#define H_    49
#define P_    (H_ * H_)        // 2401
#define PAD   51
#define PVAL  1801             // valid (unmasked) pixels per image
#define MEFF  (B_ * PVAL)      // 57632 compacted GEMM rows
#define KTOT  (7 * C_)         // 1792
#define KC    32               // K per pipeline chunk
#define NCHUNK (KTOT / KC)     // 56
#define STAGES 3
#define MT    128              // M rows per CTA
#define GRID_M ((MEFF + MT - 1) / MT)   // 451

#define A_STRIDE 40                     // floats; conflict-free LDS.64 pairs (proven R10)
#define B_STRIDE 136                    // floats; k-major B, conflict-free scalar
#define A_STAGE_F (MT * A_STRIDE)       // 5120
#define B_STAGE_F (KC * B_STRIDE)       // 4352
#define DYN_SMEM (STAGES * (A_STAGE_F + B_STAGE_F) * 4)   // 113664 bytes

// DIRS offsets in padded channels-last space: (dy*PAD+dx)*C_
__constant__ int c_tapoff[7] = { 0, 13056, 256, -12800, -13056, -256, 12800 };

// cumulative valid-pixel counts per hex row h (count = h<=24 ? 25+h : 73-h)
__constant__ int c_cum[50] = {
    0, 25, 51, 78, 106, 135, 165, 196, 228, 261, 295, 330, 366, 403, 441, 480,
    520, 561, 603, 646, 690, 735, 781, 828, 876, 925, 973, 1020, 1066, 1111,
    1155, 1198, 1240, 1281, 1321, 1360, 1398, 1435, 1471, 1506, 1540, 1573,
    1605, 1636, 1666, 1695, 1723, 1750, 1776, 1801
};

// ---------------- scratch ----------------
__device__ float g_xpad[B_ * PAD * PAD * C_];   // [B,51,51,C] channels-last, pair-perm, tf32
__device__ float g_wbT[KTOT * O_];              // [k][o], k = tap*256 + c (canonical), tf32

// A channel-pair permutation (R10, proven): within each 8-group, positions hold
// [0,4,1,5,2,6,3,7] so fragment pairs (k, k+4) are adjacent -> LDS.64.
__device__ __forceinline__ int permc(int c) {
    int c8 = c & 7;
    int p8 = (c8 < 4) ? (c8 << 1) : (((c8 - 4) << 1) | 1);
    return (c & ~7) | p8;
}

// ---------------- helpers ----------------
__device__ __forceinline__ float to_tf32(float f) {
    uint32_t u;
    asm("cvt.rna.tf32.f32 %0, %1;" : "=r"(u) : "f"(f));
    return __uint_as_float(u);
}
__device__ __forceinline__ void mma8(float* c, const uint32_t* a, uint32_t b0, uint32_t b1) {
    asm volatile(
        "mma.sync.aligned.m16n8k8.row.col.f32.tf32.tf32.f32 "
        "{%0,%1,%2,%3}, {%4,%5,%6,%7}, {%8,%9}, {%0,%1,%2,%3};"
        : "+f"(c[0]), "+f"(c[1]), "+f"(c[2]), "+f"(c[3])
        : "r"(a[0]), "r"(a[1]), "r"(a[2]), "r"(a[3]), "r"(b0), "r"(b1));
}
#define CP_ASYNC16(dst, src) \
    asm volatile("cp.async.cg.shared.global [%0], [%1], 16;" :: "r"(dst), "l"(src))
#define CP_COMMIT() asm volatile("cp.async.commit_group;")
#define CP_WAIT(n)  asm volatile("cp.async.wait_group %0;" :: "n"(n))

// ---------------- prep kernels ----------------
__global__ void zero_out_kernel(float4* __restrict__ out4) {
    int i = blockIdx.x * blockDim.x + threadIdx.x;
    const int n4 = B_ * O_ * P_ / 4;           // 4917248 / 4... (32*256*2401)/4
    if (i < (B_ * O_ * P_) / 4) out4[i] = make_float4(0.f, 0.f, 0.f, 0.f);
}

__global__ void zero_halo_kernel() {      // zero only the 200 boundary cells of xpad
    int t = blockIdx.x * blockDim.x + threadIdx.x;
    const int total = B_ * 200 * 64;
    if (t >= total) return;
    int q = t & 63;
    int cell = (t >> 6) % 200;
    int b = t / (200 * 64);
    int h, w;
    if      (cell < 51)  { h = 0;  w = cell; }
    else if (cell < 102) { h = 50; w = cell - 51; }
    else if (cell < 151) { h = cell - 101; w = 0; }
    else                 { h = cell - 150; w = 50; }
    ((float4*)(g_xpad + ((size_t)(b * PAD + h) * PAD + w) * C_))[q] =
        make_float4(0.f, 0.f, 0.f, 0.f);
}

__global__ void prep_wb_kernel(const float* __restrict__ w) {
    int idx = blockIdx.x * blockDim.x + threadIdx.x;   // idx = k*256 + o
    if (idx < KTOT * O_) {
        int o = idx & 255;
        int k = idx >> 8;
        int tap = k >> 8, c = k & 255;
        g_wbT[idx] = to_tf32(w[(o * C_ + c) * 7 + tap]);
    }
}

__global__ void prep_x_kernel(const float* __restrict__ x) {
    __shared__ float tile[32][33];
    const int b = blockIdx.z, c0 = blockIdx.y * 32, hw0 = blockIdx.x * 32;
    const int tx = threadIdx.x, ty = threadIdx.y;
#pragma unroll
    for (int i = 0; i < 4; i++) {
        int c = c0 + ty + i * 8, hw = hw0 + tx;
        tile[ty + i * 8][tx] = (hw < P_) ? x[((size_t)b * C_ + c) * P_ + hw] : 0.f;
    }
    __syncthreads();
#pragma unroll
    for (int i = 0; i < 4; i++) {
        int hw = hw0 + ty + i * 8;
        if (hw < P_) {
            int h = hw / H_, w = hw - h * H_;
            bool mk = (unsigned)(h + w - 24) <= 48u;
            float v = mk ? to_tf32(tile[tx][ty + i * 8]) : 0.f;
            g_xpad[((size_t)(b * PAD + h + 1) * PAD + (w + 1)) * C_ + permc(c0 + tx)] = v;
        }
    }
}

// ---------------- main: tf32 mma.sync GEMM over COMPACTED valid pixels ----------------
__global__ __launch_bounds__(256, 2)
void hexconv_mma_kernel(const float* __restrict__ bias, float* __restrict__ out) {
    extern __shared__ __align__(16) float smem[];
    float* sA = smem;                          // [STAGES][128][40], A pair-perm
    float* sB = smem + STAGES * A_STAGE_F;     // [STAGES][32][136], k-major
    __shared__ int rbase[MT];
    __shared__ int sh_pix[MT];                 // (b<<12) | hw for epilogue

    const int tid = threadIdx.x, wid = tid >> 5, lane = tid & 31;
    const int r0 = blockIdx.x * MT;
    const int nb = blockIdx.y;                 // N tile: o-offset nb*128

    if (tid < MT) {
        int r = r0 + tid;
        if (r >= MEFF) r = MEFF - 1;           // clamp (writes guarded later)
        int b = r / PVAL;
        int v = r - b * PVAL;                  // valid-pixel index within image
        int h = 0;                             // invert cum[]: cum[h] <= v < cum[h+1]
        while (h < 48 && v >= c_cum[h + 1]) h++;
        int wmin = (h < 24) ? (24 - h) : 0;
        int w = wmin + (v - c_cum[h]);
        rbase[tid]  = ((b * PAD + h + 1) * PAD + (w + 1)) * C_;
        sh_pix[tid] = (b << 12) | (h * H_ + w);
    }
    __syncthreads();

    // A loader: thread covers 4 rows (lrow+32i), one 16B quad per row
    const int lrow = tid >> 3;                 // 0..31
    const int lq   = (tid & 7) * 4;            // 0..28 floats (permuted positions)
    int ra[4];
#pragma unroll
    for (int i = 0; i < 4; i++) ra[i] = rbase[lrow + 32 * i];

    const uint32_t sA_u = (uint32_t)__cvta_generic_to_shared(sA);
    const uint32_t sB_u = (uint32_t)__cvta_generic_to_shared(sB);

    // warp tile: 2 (M) x 4 (N) warps, each 64x32
    const int wm = (wid & 1) * 64;
    const int wn = (wid >> 1) * 32;
    const int lq4 = lane & 3;
    const int lr4 = lane >> 2;

    float acc[4][4][4];
#pragma unroll
    for (int mi = 0; mi < 4; mi++)
#pragma unroll
        for (int ni = 0; ni < 4; ni++)
#pragma unroll
            for (int j = 0; j < 4; j++) acc[mi][ni][j] = 0.f;

    auto load_stage = [&](int s, int ch) {
        const int k0 = ch * KC;
        const int offA = c_tapoff[k0 >> 8] + (k0 & 255) + lq;
#pragma unroll
        for (int i = 0; i < 4; i++) {
            uint32_t dA = sA_u + (uint32_t)(s * A_STAGE_F + (lrow + 32 * i) * A_STRIDE + lq) * 4u;
            CP_ASYNC16(dA, g_xpad + ra[i] + offA);
        }
#pragma unroll
        for (int i = 0; i < 4; i++) {
            uint32_t dB = sB_u + (uint32_t)(s * B_STAGE_F + lrow * B_STRIDE + lq + 32 * i) * 4u;
            CP_ASYNC16(dB, g_wbT + (size_t)(k0 + lrow) * O_ + nb * 128 + lq + 32 * i);
        }
    };

#pragma unroll
    for (int s = 0; s < STAGES - 1; s++) { load_stage(s, s); CP_COMMIT(); }

    for (int ch = 0; ch < NCHUNK; ch++) {
        CP_WAIT(STAGES - 2);
        __syncthreads();
        const int pre = ch + STAGES - 1;
        if (pre < NCHUNK) load_stage(pre % STAGES, pre);
        CP_COMMIT();

        const float* A  = sA + (ch % STAGES) * A_STAGE_F;
        const float* Bm = sB + (ch % STAGES) * B_STAGE_F;
#pragma unroll
        for (int kk = 0; kk < 4; kk++) {
            const int kp = kk * 8 + 2 * lq4;   // permuted pair position (A)
            const int kb = kk * 8 + lq4;       // canonical k (B)
            uint32_t af[4][4];
#pragma unroll
            for (int mi = 0; mi < 4; mi++) {
                int m0 = wm + mi * 16 + lr4;
                float2 alo = *(const float2*)&A[m0 * A_STRIDE + kp];       // (kb, kb+4)
                float2 ahi = *(const float2*)&A[(m0 + 8) * A_STRIDE + kp];
                af[mi][0] = __float_as_uint(alo.x);
                af[mi][1] = __float_as_uint(ahi.x);
                af[mi][2] = __float_as_uint(alo.y);
                af[mi][3] = __float_as_uint(ahi.y);
            }
            uint32_t bf[4][2];
#pragma unroll
            for (int ni = 0; ni < 4; ni++) {
                int n0 = wn + ni * 8 + lr4;
                bf[ni][0] = __float_as_uint(Bm[kb * B_STRIDE + n0]);
                bf[ni][1] = __float_as_uint(Bm[(kb + 4) * B_STRIDE + n0]);
            }
#pragma unroll
            for (int mi = 0; mi < 4; mi++)
#pragma unroll
                for (int ni = 0; ni < 4; ni++)
                    mma8(acc[mi][ni], af[mi], bf[ni][0], bf[ni][1]);
        }
    }

    // ---- epilogue: acc -> smem [o][m] (stride 132), then coalesced store ----
    __syncthreads();
    float* ep = smem;                     // 128*132 floats = 67.6 KB < 111 KB
#pragma unroll
    for (int mi = 0; mi < 4; mi++) {
        int rrow = wm + mi * 16 + lr4;
#pragma unroll
        for (int ni = 0; ni < 4; ni++) {
            int o = wn + ni * 8 + 2 * lq4;
            ep[o * 132 + rrow]           = acc[mi][ni][0];
            ep[(o + 1) * 132 + rrow]     = acc[mi][ni][1];
            ep[o * 132 + rrow + 8]       = acc[mi][ni][2];
            ep[(o + 1) * 132 + rrow + 8] = acc[mi][ni][3];
        }
    }
    __syncthreads();

    for (int o = wid; o < 128; o += 8) {
        float bv = __ldg(bias + nb * 128 + o);
#pragma unroll
        for (int mb = 0; mb < 128; mb += 32) {
            int m = mb + lane;
            int r = r0 + m;
            if (r < MEFF) {
                int pix = sh_pix[m];
                int b   = pix >> 12;
                int hw  = pix & 0xFFF;
                out[((size_t)b * O_ + nb * 128 + o) * P_ + hw] = ep[o * 132 + m] + bv;
            }
        }
    }
}

// ---------------- launcher ----------------
extern "C" void kernel_launch(void* const* d_in, const int* in_sizes, int n_in,
                              void* d_out, int out_size) {
    const float* x    = (const float*)d_in[0];   // [32,256,49,49]
    const float* wgt  = (const float*)d_in[1];   // [256,256,7]
    const float* bias = (const float*)d_in[2];   // [256]
    float* out = (float*)d_out;

    { // prep
        int n4 = (B_ * O_ * P_) / 4;             // out is divisible by 4 (2401*256*32)
        zero_out_kernel<<<(n4 + 255) / 256, 256>>>((float4*)out);
        int nh = B_ * 200 * 64;
        zero_halo_kernel<<<(nh + 255) / 256, 256>>>();
        int nw = KTOT * O_;
        prep_wb_kernel<<<(nw + 255) / 256, 256>>>(wgt);
        dim3 g((P_ + 31) / 32, C_ / 32, B_);
        prep_x_kernel<<<g, dim3(32, 8)>>>(x);
    }

    cudaFuncSetAttribute(hexconv_mma_kernel,
                         cudaFuncAttributeMaxDynamicSharedMemorySize, DYN_SMEM);
    dim3 grid(GRID_M, 2);
    hexconv_mma_kernel<<<grid, 256, DYN_SMEM>>>(bias, out);
}